// round 7
// baseline (speedup 1.0000x reference)
#include <cuda_runtime.h>

namespace {
constexpr int kB   = 64;
constexpr int kN   = 883;
constexpr int kT   = 12;
constexpr int kTN  = 16;
constexpr int kTOD = 288;
constexpr int kP   = kB * kN;              // 56512 problems, 2 per warp
constexpr unsigned FM = 0xffffffffu;
} // namespace

__global__ void __launch_bounds__(256, 7) mode_att_kernel(
    const float* __restrict__ enc,
    const int*   __restrict__ xm,
    const float* __restrict__ dec,
    const float* __restrict__ kb,
    const float* __restrict__ vb,
    const float* __restrict__ aw,
    const float* __restrict__ ab,
    float*       __restrict__ out)
{
    const int warp = (blockIdx.x * blockDim.x + threadIdx.x) >> 5;
    const int lane = threadIdx.x & 31;
    const int y    = lane & 15;                // lane within 16-group
    const int p    = warp * 2 + (lane >> 4);   // problem for this half-warp
    const bool lowh = (lane & 8) == 0;

    const int b = p / kN;
    const int n = p - b * kN;
    const int t = __ldg(xm + b * 2);           // x_mark_enc[b,0,0]

    const size_t tile = ((size_t)(n * kTOD + t) * kTN) * kT;   // tile base (floats)

    // ---- K: per-row strided load (lane y owns key y) ----
    const float* __restrict__ kr = kb + tile + y * kT;
    float4 k0 = *(const float4*)(kr);
    float4 k1 = *(const float4*)(kr + 4);
    float4 k2 = *(const float4*)(kr + 8);

    // ---- V: fully coalesced tile load: lane y takes f4 #(16*i + y) ----
    const float4* __restrict__ vt4 = (const float4*)(vb + tile);
    float4 vv0 = vt4[y];
    float4 vv1 = vt4[16 + y];
    float4 vv2 = vt4[32 + y];

    // ---- Q: broadcast row ----
    const float* __restrict__ qp = enc + (size_t)p * kT;
    float4 q0 = *(const float4*)(qp);
    float4 q1 = *(const float4*)(qp + 4);
    float4 q2 = *(const float4*)(qp + 8);

    const float* __restrict__ awp = aw + n * (kTN + 1);
    const float aw_y  = __ldg(awp + y);
    const float aw_16 = __ldg(awp + 16);
    const float bias  = __ldg(ab + n);

    // Per-key squared distance.
    float dd = 0.f, df;
    df = q0.x - k0.x; dd = fmaf(df, df, dd);
    df = q0.y - k0.y; dd = fmaf(df, df, dd);
    df = q0.z - k0.z; dd = fmaf(df, df, dd);
    df = q0.w - k0.w; dd = fmaf(df, df, dd);
    df = q1.x - k1.x; dd = fmaf(df, df, dd);
    df = q1.y - k1.y; dd = fmaf(df, df, dd);
    df = q1.z - k1.z; dd = fmaf(df, df, dd);
    df = q1.w - k1.w; dd = fmaf(df, df, dd);
    df = q2.x - k2.x; dd = fmaf(df, df, dd);
    df = q2.y - k2.y; dd = fmaf(df, df, dd);
    df = q2.z - k2.z; dd = fmaf(df, df, dd);
    df = q2.w - k2.w; dd = fmaf(df, df, dd);
    const float dist = sqrtf(dd);

    // ---- wave 1: Sum(d), Sum(d^2), interleaved ----
    float s1 = dist, s2 = dd;
#pragma unroll
    for (int m = 8; m >= 1; m >>= 1) {
        s1 += __shfl_xor_sync(FM, s1, m, 16);
        s2 += __shfl_xor_sync(FM, s2, m, 16);
    }

    // ---- softmax stats (raw moments; |score| <= 37.5, no max-sub needed) ----
    const float mean = s1 * (1.0f / 16.0f);
    const float var  = fmaxf((s2 - s1 * mean) * (1.0f / 15.0f), 0.0f);
    const float istd = __fdividef(10.0f, sqrtf(var) + 1e-6f);
    const float ex   = __expf((mean - dist) * istd);

    const float d16    = 0.34641016151377545871f;
    const float s1b    = s1 + d16;
    const float mean17 = s1b * (1.0f / 17.0f);
    const float var17  = fmaxf((s2 + d16 * d16 - s1b * mean17) * (1.0f / 16.0f), 0.0f);
    const float istd2  = __fdividef(10.0f, sqrtf(var17) + 1e-6f);
    const float e2     = __expf((mean17 - dist) * istd2);
    const float e16    = __expf((mean17 - d16)  * istd2);

    // ---- redistribute ex to match coalesced V: eb[i] = ex of key (16i+y)/3 ----
    const float eb0 = __shfl_sync(FM, ex, (y)      / 3, 16);
    const float eb1 = __shfl_sync(FM, ex, (16 + y) / 3, 16);
    const float eb2 = __shfl_sync(FM, ex, (32 + y) / 3, 16);

    // Slot alignment: pass i covers output f4-slot c = (y + i) % 3.
    const int r3 = y % 3;
    float o[12];
#pragma unroll
    for (int c = 0; c < 3; ++c) {
        int pc = c - r3; pc += (pc < 0) ? 3 : 0;
        const float4 vs  = (pc == 0) ? vv0 : ((pc == 1) ? vv1 : vv2);
        const float  es_ = (pc == 0) ? eb0 : ((pc == 1) ? eb1 : eb2);
        o[c * 4 + 0] = es_ * vs.x;
        o[c * 4 + 1] = es_ * vs.y;
        o[c * 4 + 2] = es_ * vs.z;
        o[c * 4 + 3] = es_ * vs.w;
    }

    // ---- wave 2: m=8 on {es,es2,ea,o[12]}, fold dims, finish on 9 values ----
    float es = ex, es2 = e2, ea = e2 * aw_y;
    es  += __shfl_xor_sync(FM, es,  8, 16);
    es2 += __shfl_xor_sync(FM, es2, 8, 16);
    ea  += __shfl_xor_sync(FM, ea,  8, 16);
#pragma unroll
    for (int d = 0; d < 12; ++d)
        o[d] += __shfl_xor_sync(FM, o[d], 8, 16);

    float r[6];
#pragma unroll
    for (int d = 0; d < 6; ++d)
        r[d] = lowh ? o[d] : o[d + 6];

#pragma unroll
    for (int m = 4; m >= 1; m >>= 1) {
        es  += __shfl_xor_sync(FM, es,  m, 16);
        es2 += __shfl_xor_sync(FM, es2, m, 16);
        ea  += __shfl_xor_sync(FM, ea,  m, 16);
#pragma unroll
        for (int d = 0; d < 6; ++d)
            r[d] += __shfl_xor_sync(FM, r[d], m, 16);
    }

    // ---- gate, blend, write: lanes sub=0,1,2 of each 8-subgroup write float2 ----
    const float inv2 = __fdividef(1.0f, es2 + e16);
    const float w    = (ea + e16 * aw_16) * inv2 + bias;
    const float omw  = (1.0f - w) * __fdividef(1.0f, es);

    const int sub = lane & 7;
    if (sub < 3) {
        const size_t base = (size_t)p * kT + (lowh ? 0 : 6) + 2 * sub;
        float2 d2 = *(const float2*)(dec + base);
        float2 r2 = make_float2(fmaf(omw, r[2 * sub],     w * d2.x),
                                fmaf(omw, r[2 * sub + 1], w * d2.y));
        *(float2*)(out + base) = r2;
    }
}

extern "C" void kernel_launch(void* const* d_in, const int* in_sizes, int n_in,
                              void* d_out, int out_size) {
    const float* enc = (const float*)d_in[0];
    const int*   xm  = (const int*)  d_in[1];
    const float* dec = (const float*)d_in[2];
    const float* kb  = (const float*)d_in[3];
    const float* vb  = (const float*)d_in[4];
    const float* aw  = (const float*)d_in[5];
    const float* ab  = (const float*)d_in[6];
    float*       out = (float*)d_out;

    const int problems_per_block = 16;            // 8 warps * 2
    const int blocks = kP / problems_per_block;   // 3532 (exact)
    mode_att_kernel<<<blocks, 256>>>(enc, xm, dec, kb, vb, aw, ab, out);
}

// round 8
// speedup vs baseline: 1.1508x; 1.1508x over previous
#include <cuda_runtime.h>

namespace {
constexpr int kB   = 64;
constexpr int kN   = 883;
constexpr int kT   = 12;
constexpr int kTN  = 16;
constexpr int kTOD = 288;
constexpr int kP   = kB * kN;              // 56512 problems, 2 per warp
constexpr unsigned FM = 0xffffffffu;
} // namespace

__global__ void __launch_bounds__(256) mode_att_kernel(
    const float* __restrict__ enc,
    const int*   __restrict__ xm,
    const float* __restrict__ dec,
    const float* __restrict__ kb,
    const float* __restrict__ vb,
    const float* __restrict__ aw,
    const float* __restrict__ ab,
    float*       __restrict__ out)
{
    const int warp = (blockIdx.x * blockDim.x + threadIdx.x) >> 5;
    const int lane = threadIdx.x & 31;
    const int y    = lane & 15;
    const int p    = warp * 2 + (lane >> 4);   // problem for this half-warp
    const bool lowh = (lane & 8) == 0;

    const int b = p / kN;
    const int n = p - b * kN;
    const int t = __ldg(xm + b * 2);           // x_mark_enc[b,0,0]

    const size_t rbase = ((size_t)((n * kTOD + t) * kTN + y)) * kT;
    const float* __restrict__ kr = kb + rbase;
    const float* __restrict__ vr = vb + rbase;

    // Front-batched loads for MLP.
    float4 k0 = *(const float4*)(kr);
    float4 k1 = *(const float4*)(kr + 4);
    float4 k2 = *(const float4*)(kr + 8);
    float4 v0 = *(const float4*)(vr);
    float4 v1 = *(const float4*)(vr + 4);
    float4 v2 = *(const float4*)(vr + 8);

    const float* __restrict__ qp = enc + (size_t)p * kT;
    float4 q0 = *(const float4*)(qp);
    float4 q1 = *(const float4*)(qp + 4);
    float4 q2 = *(const float4*)(qp + 8);

    const float* __restrict__ awp = aw + n * (kTN + 1);
    const float aw_y  = __ldg(awp + y);
    const float aw_16 = __ldg(awp + 16);
    const float bias  = __ldg(ab + n);

    // Per-key squared distance.
    float dd = 0.f, df;
    df = q0.x - k0.x; dd = fmaf(df, df, dd);
    df = q0.y - k0.y; dd = fmaf(df, df, dd);
    df = q0.z - k0.z; dd = fmaf(df, df, dd);
    df = q0.w - k0.w; dd = fmaf(df, df, dd);
    df = q1.x - k1.x; dd = fmaf(df, df, dd);
    df = q1.y - k1.y; dd = fmaf(df, df, dd);
    df = q1.z - k1.z; dd = fmaf(df, df, dd);
    df = q1.w - k1.w; dd = fmaf(df, df, dd);
    df = q2.x - k2.x; dd = fmaf(df, df, dd);
    df = q2.y - k2.y; dd = fmaf(df, df, dd);
    df = q2.z - k2.z; dd = fmaf(df, df, dd);
    df = q2.w - k2.w; dd = fmaf(df, df, dd);
    const float dist = sqrtf(dd);

    // ---- reduction wave 1: Sum(d) and Sum(d^2), interleaved ----
    float s1 = dist, s2 = dd;
#pragma unroll
    for (int m = 8; m >= 1; m >>= 1) {
        s1 += __shfl_xor_sync(FM, s1, m, 16);
        s2 += __shfl_xor_sync(FM, s2, m, 16);
    }

    // First softmax stats (raw moments, ddof=1; |score| <= 37.5, no max-sub).
    const float mean = s1 * (1.0f / 16.0f);
    const float var  = fmaxf((s2 - s1 * mean) * (1.0f / 15.0f), 0.0f);
    const float istd = __fdividef(10.0f, sqrtf(var) + 1e-6f);
    const float ex   = __expf((mean - dist) * istd);

    // Second softmax stats over 17 keys (17th = Q+0.1, dist = sqrt(12*0.01)).
    const float d16    = 0.34641016151377545871f;
    const float s1b    = s1 + d16;
    const float mean17 = s1b * (1.0f / 17.0f);
    const float var17  = fmaxf((s2 + d16 * d16 - s1b * mean17) * (1.0f / 16.0f), 0.0f);
    const float istd2  = __fdividef(10.0f, sqrtf(var17) + 1e-6f);
    const float e2     = __expf((mean17 - dist) * istd2);
    const float e16    = __expf((mean17 - d16)  * istd2);

    // ---- wave 2: m=8 round on {es, es2, ea, o[0..11]} ----
    float es = ex, es2 = e2, ea = e2 * aw_y;
    float o[12];
    o[0] = ex * v0.x; o[1]  = ex * v0.y; o[2]  = ex * v0.z; o[3]  = ex * v0.w;
    o[4] = ex * v1.x; o[5]  = ex * v1.y; o[6]  = ex * v1.z; o[7]  = ex * v1.w;
    o[8] = ex * v2.x; o[9]  = ex * v2.y; o[10] = ex * v2.z; o[11] = ex * v2.w;

    es  += __shfl_xor_sync(FM, es,  8, 16);
    es2 += __shfl_xor_sync(FM, es2, 8, 16);
    ea  += __shfl_xor_sync(FM, ea,  8, 16);
#pragma unroll
    for (int d = 0; d < 12; ++d)
        o[d] += __shfl_xor_sync(FM, o[d], 8, 16);

    // Fold: low 8-subgroup carries dims 0-5, high subgroup dims 6-11.
    float r[6];
#pragma unroll
    for (int d = 0; d < 6; ++d)
        r[d] = lowh ? o[d] : o[d + 6];

#pragma unroll
    for (int m = 4; m >= 1; m >>= 1) {
        es  += __shfl_xor_sync(FM, es,  m, 16);
        es2 += __shfl_xor_sync(FM, es2, m, 16);
        ea  += __shfl_xor_sync(FM, ea,  m, 16);
#pragma unroll
        for (int d = 0; d < 6; ++d)
            r[d] += __shfl_xor_sync(FM, r[d], m, 16);
    }

    // Gate weight; fold prob normalization into the blend.
    const float inv2 = __fdividef(1.0f, es2 + e16);
    const float w    = (ea + e16 * aw_16) * inv2 + bias;
    const float omw  = (1.0f - w) * __fdividef(1.0f, es);

    // ---- blend and write: lanes sub=0,1,2 of each 8-subgroup write float2 ----
    const int sub = lane & 7;
    if (sub < 3) {
        const size_t base = (size_t)p * kT + (lowh ? 0 : 6) + 2 * sub;
        float2 d2 = *(const float2*)(dec + base);
        float2 r2 = make_float2(fmaf(omw, r[2 * sub],     w * d2.x),
                                fmaf(omw, r[2 * sub + 1], w * d2.y));
        *(float2*)(out + base) = r2;
    }
}

extern "C" void kernel_launch(void* const* d_in, const int* in_sizes, int n_in,
                              void* d_out, int out_size) {
    const float* enc = (const float*)d_in[0];
    const int*   xm  = (const int*)  d_in[1];
    const float* dec = (const float*)d_in[2];
    const float* kb  = (const float*)d_in[3];
    const float* vb  = (const float*)d_in[4];
    const float* aw  = (const float*)d_in[5];
    const float* ab  = (const float*)d_in[6];
    float*       out = (float*)d_out;

    const int problems_per_block = 16;            // 8 warps * 2
    const int blocks = kP / problems_per_block;   // 3532 (exact)
    mode_att_kernel<<<blocks, 256>>>(enc, xm, dec, kb, vb, aw, ab, out);
}